// round 13
// baseline (speedup 1.0000x reference)
#include <cuda_runtime.h>
#include <cstdint>

// Problem constants (fixed shapes)
#define BS    16
#define DIM   4096
#define NH    32
#define DH    128
#define SEQ   4096
#define NCOL  4096   // NH*DH
#define KS    64     // K-split for the 16xN GEMMs

#define WEIGHT_ELEMS (BS * NH * SEQ)   // 2097152
#define BN (BS * NCOL)                 // 65536

// Scratch (device globals; no allocation allowed)
__device__ float g_qkv[3 * BN];             // q,k,v : [mat][b][h*128+d]
__device__ float g_part[3 * KS * BN];       // qkv GEMM k-split partials (L2-resident)
__device__ float g_ctx[BN];                 // attention context [b][h*128+d]
__device__ float g_cpart[KS * BN];          // out-proj k-split partials (L2-resident)

// ---------------------------------------------------------------------------
// 16xK @ KxN GEMM body, batch-split layout:
//   128 threads = 64 column-pairs x 2 batch-halves.
//   Thread owns 2 consecutive output columns x 8 batch rows (one half).
//   acc = 8 u64 (fma.rn.f32x2, 2 batches/instr), W batched 16-deep
//   (16 independent LDG.64 in flight = 128B/thread; the sibling half's warp
//   re-reads the same W line -> L1 hit). Total regs ~60 <= 64 so
//   launch_bounds(128,8) keeps 32 warps/SM.
//   Block covers 128 columns and DIM/KS = 64 K-rows.
// ---------------------------------------------------------------------------
__device__ __forceinline__ void gemm16_body(const float* __restrict__ X,
                                            const float* __restrict__ W,
                                            float* __restrict__ part)
{
    __shared__ __align__(16) float xs[64][16];
    const int jc   = threadIdx.x & 63;                   // column-pair in block
    const int half = threadIdx.x >> 6;                   // batch half (0/1)
    const int j2   = blockIdx.x * 64 + jc;               // global float2 col idx
    const int d0   = blockIdx.y * (DIM / KS);            // 64 rows per split

#pragma unroll
    for (int i = threadIdx.x; i < 1024; i += 128) {
        int b = i >> 6, dd = i & 63;
        xs[dd][b] = X[b * DIM + d0 + dd];
    }

    // acc[p*2+c]: batches {half*8+2p, half*8+2p+1}, column c of the pair
    unsigned long long acc[8];
#pragma unroll
    for (int i = 0; i < 8; i++) acc[i] = 0ull;

    const float2* W2 = (const float2*)W + j2;
    const uint32_t xs_sh = (uint32_t)__cvta_generic_to_shared(&xs[0][0]) + half * 32;

    __syncthreads();

#pragma unroll
    for (int g = 0; g < 4; g++) {
        float2 w[16];
        // 16 independent LDG.64 back-to-back (128B in flight per thread)
#pragma unroll
        for (int r = 0; r < 16; r++)
            w[r] = W2[(size_t)(d0 + g * 16 + r) * (NCOL / 2)];
#pragma unroll
        for (int r = 0; r < 16; r++) {
            unsigned long long wx, wy;
            asm("mov.b64 %0, {%1, %1};" : "=l"(wx) : "f"(w[r].x));
            asm("mov.b64 %0, {%1, %1};" : "=l"(wy) : "f"(w[r].y));
            const uint32_t ra = xs_sh + (g * 16 + r) * 64;
            unsigned long long xa, xb, xc, xd;   // 8 batches of this half
            asm("ld.shared.v2.b64 {%0, %1}, [%2];"      : "=l"(xa), "=l"(xb) : "r"(ra));
            asm("ld.shared.v2.b64 {%0, %1}, [%2+16];"   : "=l"(xc), "=l"(xd) : "r"(ra));
            asm("fma.rn.f32x2 %0, %1, %2, %0;" : "+l"(acc[0]) : "l"(xa), "l"(wx));
            asm("fma.rn.f32x2 %0, %1, %2, %0;" : "+l"(acc[1]) : "l"(xa), "l"(wy));
            asm("fma.rn.f32x2 %0, %1, %2, %0;" : "+l"(acc[2]) : "l"(xb), "l"(wx));
            asm("fma.rn.f32x2 %0, %1, %2, %0;" : "+l"(acc[3]) : "l"(xb), "l"(wy));
            asm("fma.rn.f32x2 %0, %1, %2, %0;" : "+l"(acc[4]) : "l"(xc), "l"(wx));
            asm("fma.rn.f32x2 %0, %1, %2, %0;" : "+l"(acc[5]) : "l"(xc), "l"(wy));
            asm("fma.rn.f32x2 %0, %1, %2, %0;" : "+l"(acc[6]) : "l"(xd), "l"(wx));
            asm("fma.rn.f32x2 %0, %1, %2, %0;" : "+l"(acc[7]) : "l"(xd), "l"(wy));
        }
    }

    // store this half's 8 batches
    float2* P2 = (float2*)part;
#pragma unroll
    for (int p = 0; p < 4; p++) {
        float c0l, c0h, c1l, c1h;
        asm("mov.b64 {%0, %1}, %2;" : "=f"(c0l), "=f"(c0h) : "l"(acc[p * 2]));
        asm("mov.b64 {%0, %1}, %2;" : "=f"(c1l), "=f"(c1h) : "l"(acc[p * 2 + 1]));
        const int b0 = half * 8 + p * 2;
        P2[(b0 + 0) * (NCOL / 2) + j2] = make_float2(c0l, c1l);
        P2[(b0 + 1) * (NCOL / 2) + j2] = make_float2(c0h, c1h);
    }
}

__global__ __launch_bounds__(128, 8)
void gemm_qkv(const float* __restrict__ x, const float* __restrict__ wq,
              const float* __restrict__ wk, const float* __restrict__ wv)
{
    const float* W = (blockIdx.z == 0) ? wq : (blockIdx.z == 1 ? wk : wv);
    float* part = g_part + ((size_t)blockIdx.z * KS + blockIdx.y) * BN;
    gemm16_body(x, W, part);
}

__global__ __launch_bounds__(128, 8)
void gemm_out(const float* __restrict__ wo)
{
    float* part = g_cpart + (size_t)blockIdx.y * BN;
    gemm16_body(g_ctx, wo, part);
}

__global__ __launch_bounds__(256)
void reduce_qkv()
{
    int i = blockIdx.x * 256 + threadIdx.x;
    if (i < 3 * BN) {
        int mat = i >> 16;
        int r   = i & (BN - 1);
        const float* p = g_part + (size_t)mat * KS * BN + r;
        float s = 0.f;
#pragma unroll 8
        for (int k = 0; k < KS; k++) s += p[(size_t)k * BN];
        g_qkv[i] = s;
    }
}

__global__ __launch_bounds__(256)
void reduce_out(float* __restrict__ out)
{
    int i = blockIdx.x * 256 + threadIdx.x;
    if (i < BN) {
        const float* p = g_cpart + i;
        float s = 0.f;
#pragma unroll 8
        for (int k = 0; k < KS; k++) s += p[(size_t)k * BN];
        out[i] = s;
    }
}

// ---------------------------------------------------------------------------
// Fused attention per (b,h), 512 threads — two-pass form (rounds 4/7/9;
// ~6.6 TB/s effective ~94% of achievable HBM; single wave of 512 resident
// blocks). DO NOT SPLIT: splitting added a second wave + overhead and
// regressed +30us twice (rounds 3, 6, 8).
// ---------------------------------------------------------------------------
__global__ __launch_bounds__(512)
void attn_kernel(const float* __restrict__ ck, const float* __restrict__ cv,
                 const float* __restrict__ mask, float* __restrict__ out)
{
    const int b = blockIdx.x, h = blockIdx.y;
    const int tid = threadIdx.x, lane = tid & 31, wp = tid >> 5;

    __shared__ float sc[SEQ];          // scores -> exp weights
    __shared__ __align__(16) float qs[DH];
    __shared__ float redm[16], reds[16];
    __shared__ __align__(16) float cp[16][DH];

    if (tid < DH) qs[tid] = g_qkv[(size_t)b * NCOL + h * DH + tid];
    __syncthreads();

    const float4 qf = ((const float4*)qs)[lane];
    const float* kbase = ck + ((size_t)b << 24) + (size_t)h * DH;   // b*SEQ*NCOL
    const float* knew  = g_qkv + BN + (size_t)b * NCOL + h * DH;    // xk row
    const float scale = 0.08838834764831845f;                        // 1/sqrt(128)
    float* wout = out + ((size_t)(b * NH + h)) * SEQ;

    // pass 1: scores (16 warps, 256 rows each)
#pragma unroll 4
    for (int k = wp; k < SEQ; k += 16) {
        const float* row = (k == SEQ - 1) ? knew : (kbase + (size_t)k * NCOL);
        float4 kf = ((const float4*)row)[lane];
        float p = kf.x * qf.x + kf.y * qf.y + kf.z * qf.z + kf.w * qf.w;
        p += __shfl_xor_sync(0xffffffffu, p, 16);
        p += __shfl_xor_sync(0xffffffffu, p, 8);
        p += __shfl_xor_sync(0xffffffffu, p, 4);
        p += __shfl_xor_sync(0xffffffffu, p, 2);
        p += __shfl_xor_sync(0xffffffffu, p, 1);
        if (lane == 0) sc[k] = p * scale + mask[k];
    }
    __syncthreads();

    // coalesced weight output write + max reduce
    float m = -1e30f;
    for (int i = tid; i < SEQ; i += 512) {
        float s = sc[i];
        wout[i] = s;
        m = fmaxf(m, s);
    }
#pragma unroll
    for (int o = 16; o; o >>= 1) m = fmaxf(m, __shfl_xor_sync(0xffffffffu, m, o));
    if (lane == 0) redm[wp] = m;
    __syncthreads();
    float M = redm[0];
#pragma unroll
    for (int i = 1; i < 16; i++) M = fmaxf(M, redm[i]);

    float sum = 0.f;
    for (int i = tid; i < SEQ; i += 512) {
        float e = __expf(sc[i] - M);
        sc[i] = e;
        sum += e;
    }
#pragma unroll
    for (int o = 16; o; o >>= 1) sum += __shfl_xor_sync(0xffffffffu, sum, o);
    if (lane == 0) reds[wp] = sum;
    __syncthreads();
    float S = 0.f;
#pragma unroll
    for (int i = 0; i < 16; i++) S += reds[i];
    const float rinv = 1.f / S;

    // pass 2: ctx[d] = sum_k attn[k] * V[b,k,h,d]; 16 k-stripes, float4 loads
    const float4* vrow4 = (const float4*)(cv + ((size_t)b << 24) + (size_t)h * DH);
    float4 a4 = make_float4(0.f, 0.f, 0.f, 0.f);
    const int k0 = wp * 256;
    const int k1 = k0 + 256 - (wp == 15 ? 1 : 0);   // stripe 15 stops at 4094
#pragma unroll 8
    for (int k = k0; k < k1; k++) {
        float w = sc[k];
        float4 v = vrow4[(size_t)k * (NCOL / 4) + lane];
        a4.x += w * v.x; a4.y += w * v.y; a4.z += w * v.z; a4.w += w * v.w;
    }
    if (wp == 15) {
        float w = sc[SEQ - 1];
        float4 v = ((const float4*)(g_qkv + 2 * BN + (size_t)b * NCOL + h * DH))[lane];
        a4.x += w * v.x; a4.y += w * v.y; a4.z += w * v.z; a4.w += w * v.w;
    }
    ((float4*)cp[wp])[lane] = a4;
    __syncthreads();

    if (tid < DH) {
        float s = 0.f;
#pragma unroll
        for (int i = 0; i < 16; i++) s += cp[i][tid];
        g_ctx[(size_t)b * NCOL + h * DH + tid] = s * rinv;
    }
}

// ---------------------------------------------------------------------------
extern "C" void kernel_launch(void* const* d_in, const int* in_sizes, int n_in,
                              void* d_out, int out_size)
{
    const float* x    = (const float*)d_in[0];
    const float* mask = (const float*)d_in[1];
    const float* wq   = (const float*)d_in[2];
    const float* wk   = (const float*)d_in[3];
    const float* wv   = (const float*)d_in[4];
    const float* wo   = (const float*)d_in[5];
    const float* ck   = (const float*)d_in[6];
    const float* cv   = (const float*)d_in[7];
    float* out = (float*)d_out;

    gemm_qkv<<<dim3(32, KS, 3), 128>>>(x, wq, wk, wv);
    reduce_qkv<<<(3 * BN) / 256, 256>>>();
    attn_kernel<<<dim3(BS, NH), 512>>>(ck, cv, mask, out);
    gemm_out<<<dim3(32, KS, 1), 128>>>(wo);
    reduce_out<<<BN / 256, 256>>>(out + WEIGHT_ELEMS);
}

// round 14
// speedup vs baseline: 1.0488x; 1.0488x over previous
#include <cuda_runtime.h>
#include <cstdint>

// Problem constants (fixed shapes)
#define BS    16
#define DIM   4096
#define NH    32
#define DH    128
#define SEQ   4096
#define NCOL  4096   // NH*DH
#define KS    64     // K-split for the 16xN GEMMs

#define WEIGHT_ELEMS (BS * NH * SEQ)   // 2097152
#define BN (BS * NCOL)                 // 65536

// Scratch (device globals; no allocation allowed)
__device__ float g_qkv[3 * BN];             // q,k,v : [mat][b][h*128+d]
__device__ float g_part[3 * KS * BN];       // qkv GEMM k-split partials (L2-resident)
__device__ float g_ctx[BN];                 // attention context [b][h*128+d]
__device__ float g_cpart[KS * BN];          // out-proj k-split partials (L2-resident)

// ---------------------------------------------------------------------------
// 16xK @ KxN GEMM body (round-12 best: 3.46 TB/s): 128 threads, each thread
// owns 2 consecutive output columns for all 16 batch rows (fma.rn.f32x2).
// All 64 K-rows of X staged once in smem (broadcast LDS.128 reads). W loads
// batched 8-deep (8 independent LDG.64; each W line read exactly once per
// block -> minimal l1tex pressure). regs = 64, launch_bounds(128,8).
// ---------------------------------------------------------------------------
__device__ __forceinline__ void gemm16_body(const float* __restrict__ X,
                                            const float* __restrict__ W,
                                            float* __restrict__ part)
{
    __shared__ __align__(16) float xs[64][16];
    const int j2 = blockIdx.x * 128 + threadIdx.x;       // float2 column index
    const int d0 = blockIdx.y * (DIM / KS);              // 64 rows per split

#pragma unroll
    for (int i = threadIdx.x; i < 1024; i += 128) {
        int b = i >> 6, dd = i & 63;
        xs[dd][b] = X[b * DIM + d0 + dd];
    }

    unsigned long long acc[16];
#pragma unroll
    for (int i = 0; i < 16; i++) acc[i] = 0ull;

    const float2* W2 = (const float2*)W + j2;
    const uint32_t xs_sh = (uint32_t)__cvta_generic_to_shared(&xs[0][0]);

    __syncthreads();

#pragma unroll
    for (int g = 0; g < 8; g++) {
        float2 w[8];
        // 8 independent LDG.64 back-to-back
#pragma unroll
        for (int r = 0; r < 8; r++)
            w[r] = W2[(size_t)(d0 + g * 8 + r) * (NCOL / 2)];
#pragma unroll
        for (int r = 0; r < 8; r++) {
            unsigned long long wx, wy;
            asm("mov.b64 %0, {%1, %1};" : "=l"(wx) : "f"(w[r].x));
            asm("mov.b64 %0, {%1, %1};" : "=l"(wy) : "f"(w[r].y));
            const uint32_t ra = xs_sh + (g * 8 + r) * 64;
#pragma unroll
            for (int bh = 0; bh < 4; bh++) {
                unsigned long long xa, xb;   // batches {4bh,4bh+1}, {4bh+2,4bh+3}
                asm("ld.shared.v2.b64 {%0, %1}, [%2];"
                    : "=l"(xa), "=l"(xb) : "r"(ra + bh * 16));
                asm("fma.rn.f32x2 %0, %1, %2, %0;" : "+l"(acc[bh * 4 + 0]) : "l"(xa), "l"(wx));
                asm("fma.rn.f32x2 %0, %1, %2, %0;" : "+l"(acc[bh * 4 + 1]) : "l"(xa), "l"(wy));
                asm("fma.rn.f32x2 %0, %1, %2, %0;" : "+l"(acc[bh * 4 + 2]) : "l"(xb), "l"(wx));
                asm("fma.rn.f32x2 %0, %1, %2, %0;" : "+l"(acc[bh * 4 + 3]) : "l"(xb), "l"(wy));
            }
        }
    }

    float2* P2 = (float2*)part;
#pragma unroll
    for (int bp = 0; bp < 8; bp++) {
        float c0l, c0h, c1l, c1h;
        asm("mov.b64 {%0, %1}, %2;" : "=f"(c0l), "=f"(c0h) : "l"(acc[bp * 2]));
        asm("mov.b64 {%0, %1}, %2;" : "=f"(c1l), "=f"(c1h) : "l"(acc[bp * 2 + 1]));
        P2[(bp * 2 + 0) * (NCOL / 2) + j2] = make_float2(c0l, c1l);
        P2[(bp * 2 + 1) * (NCOL / 2) + j2] = make_float2(c0h, c1h);
    }
}

__global__ __launch_bounds__(128, 8)
void gemm_qkv(const float* __restrict__ x, const float* __restrict__ wq,
              const float* __restrict__ wk, const float* __restrict__ wv)
{
    const float* W = (blockIdx.z == 0) ? wq : (blockIdx.z == 1 ? wk : wv);
    float* part = g_part + ((size_t)blockIdx.z * KS + blockIdx.y) * BN;
    gemm16_body(x, W, part);
}

__global__ __launch_bounds__(128, 8)
void gemm_out(const float* __restrict__ wo)
{
    float* part = g_cpart + (size_t)blockIdx.y * BN;
    gemm16_body(g_ctx, wo, part);
}

__global__ __launch_bounds__(256)
void reduce_qkv()
{
    int i = blockIdx.x * 256 + threadIdx.x;
    if (i < 3 * BN) {
        int mat = i >> 16;
        int r   = i & (BN - 1);
        const float* p = g_part + (size_t)mat * KS * BN + r;
        float s = 0.f;
#pragma unroll 8
        for (int k = 0; k < KS; k++) s += p[(size_t)k * BN];
        g_qkv[i] = s;
    }
}

__global__ __launch_bounds__(256)
void reduce_out(float* __restrict__ out)
{
    int i = blockIdx.x * 256 + threadIdx.x;
    if (i < BN) {
        const float* p = g_cpart + i;
        float s = 0.f;
#pragma unroll 8
        for (int k = 0; k < KS; k++) s += p[(size_t)k * BN];
        out[i] = s;
    }
}

// ---------------------------------------------------------------------------
// Fused attention per (b,h), 512 threads — two-pass form (rounds 4/7/9/12;
// ~6.6 TB/s effective; single wave of 512 resident blocks). DO NOT SPLIT
// (regressed +30us in rounds 3, 6, 8). This round: K/V streamed with __ldcs
// (evict-first — the 2.15GB stream is never reused; keeps L2 from thrashing).
// ---------------------------------------------------------------------------
__global__ __launch_bounds__(512)
void attn_kernel(const float* __restrict__ ck, const float* __restrict__ cv,
                 const float* __restrict__ mask, float* __restrict__ out)
{
    const int b = blockIdx.x, h = blockIdx.y;
    const int tid = threadIdx.x, lane = tid & 31, wp = tid >> 5;

    __shared__ float sc[SEQ];          // scores -> exp weights
    __shared__ __align__(16) float qs[DH];
    __shared__ float redm[16], reds[16];
    __shared__ __align__(16) float cp[16][DH];

    if (tid < DH) qs[tid] = g_qkv[(size_t)b * NCOL + h * DH + tid];
    __syncthreads();

    const float4 qf = ((const float4*)qs)[lane];
    const float4* kb4 = (const float4*)(ck + ((size_t)b << 24) + (size_t)h * DH);
    const float4* kn4 = (const float4*)(g_qkv + BN + (size_t)b * NCOL + h * DH);
    const float scale = 0.08838834764831845f;                        // 1/sqrt(128)
    float* wout = out + ((size_t)(b * NH + h)) * SEQ;

    // pass 1: scores (16 warps, 256 rows each); streaming K loads
#pragma unroll 4
    for (int k = wp; k < SEQ; k += 16) {
        float4 kf = (k == SEQ - 1) ? kn4[lane]
                                   : __ldcs(&kb4[(size_t)k * (NCOL / 4) + lane]);
        float p = kf.x * qf.x + kf.y * qf.y + kf.z * qf.z + kf.w * qf.w;
        p += __shfl_xor_sync(0xffffffffu, p, 16);
        p += __shfl_xor_sync(0xffffffffu, p, 8);
        p += __shfl_xor_sync(0xffffffffu, p, 4);
        p += __shfl_xor_sync(0xffffffffu, p, 2);
        p += __shfl_xor_sync(0xffffffffu, p, 1);
        if (lane == 0) sc[k] = p * scale + __ldg(&mask[k]);
    }
    __syncthreads();

    // coalesced weight output write + max reduce
    float m = -1e30f;
    for (int i = tid; i < SEQ; i += 512) {
        float s = sc[i];
        wout[i] = s;
        m = fmaxf(m, s);
    }
#pragma unroll
    for (int o = 16; o; o >>= 1) m = fmaxf(m, __shfl_xor_sync(0xffffffffu, m, o));
    if (lane == 0) redm[wp] = m;
    __syncthreads();
    float M = redm[0];
#pragma unroll
    for (int i = 1; i < 16; i++) M = fmaxf(M, redm[i]);

    float sum = 0.f;
    for (int i = tid; i < SEQ; i += 512) {
        float e = __expf(sc[i] - M);
        sc[i] = e;
        sum += e;
    }
#pragma unroll
    for (int o = 16; o; o >>= 1) sum += __shfl_xor_sync(0xffffffffu, sum, o);
    if (lane == 0) reds[wp] = sum;
    __syncthreads();
    float S = 0.f;
#pragma unroll
    for (int i = 0; i < 16; i++) S += reds[i];
    const float rinv = 1.f / S;

    // pass 2: ctx[d] = sum_k attn[k] * V[b,k,h,d]; 16 k-stripes, streaming
    const float4* vrow4 = (const float4*)(cv + ((size_t)b << 24) + (size_t)h * DH);
    float4 a4 = make_float4(0.f, 0.f, 0.f, 0.f);
    const int k0 = wp * 256;
    const int k1 = k0 + 256 - (wp == 15 ? 1 : 0);   // stripe 15 stops at 4094
#pragma unroll 8
    for (int k = k0; k < k1; k++) {
        float w = sc[k];
        float4 v = __ldcs(&vrow4[(size_t)k * (NCOL / 4) + lane]);
        a4.x += w * v.x; a4.y += w * v.y; a4.z += w * v.z; a4.w += w * v.w;
    }
    if (wp == 15) {
        float w = sc[SEQ - 1];
        float4 v = ((const float4*)(g_qkv + 2 * BN + (size_t)b * NCOL + h * DH))[lane];
        a4.x += w * v.x; a4.y += w * v.y; a4.z += w * v.z; a4.w += w * v.w;
    }
    ((float4*)cp[wp])[lane] = a4;
    __syncthreads();

    if (tid < DH) {
        float s = 0.f;
#pragma unroll
        for (int i = 0; i < 16; i++) s += cp[i][tid];
        g_ctx[(size_t)b * NCOL + h * DH + tid] = s * rinv;
    }
}

// ---------------------------------------------------------------------------
extern "C" void kernel_launch(void* const* d_in, const int* in_sizes, int n_in,
                              void* d_out, int out_size)
{
    const float* x    = (const float*)d_in[0];
    const float* mask = (const float*)d_in[1];
    const float* wq   = (const float*)d_in[2];
    const float* wk   = (const float*)d_in[3];
    const float* wv   = (const float*)d_in[4];
    const float* wo   = (const float*)d_in[5];
    const float* ck   = (const float*)d_in[6];
    const float* cv   = (const float*)d_in[7];
    float* out = (float*)d_out;

    gemm_qkv<<<dim3(16, KS, 3), 128>>>(x, wq, wk, wv);
    reduce_qkv<<<(3 * BN) / 256, 256>>>();
    attn_kernel<<<dim3(BS, NH), 512>>>(ck, cv, mask, out);
    gemm_out<<<dim3(16, KS, 1), 128>>>(wo);
    reduce_out<<<BN / 256, 256>>>(out + WEIGHT_ELEMS);
}